// round 15
// baseline (speedup 1.0000x reference)
#include <cuda_runtime.h>
#include <cuda_bf16.h>
#include <math.h>
#include <float.h>
#include <stdint.h>

#define B_   128
#define T_   1000
#define ROWS_ (B_*T_)

// ---------------- device scratch (no allocs allowed) ----------------
__device__ float g_qpart[B_*256];
__device__ float g_rsig[B_*256];
__device__ float g_relp[2][ROWS_];
__device__ uint4 g_wchunks[8*2048];   // 8 chunks x 32KB swizzled SMEM images of Wh/Wl, [n][k] layout

// ---------------- helpers ----------------
__device__ __forceinline__ float gelu_f(float v) {
    return 0.5f * v * (1.0f + erff(v * 0.7071067811865475f));
}
__device__ __forceinline__ float warpSum(float v) {
#pragma unroll
    for (int o = 16; o > 0; o >>= 1) v += __shfl_down_sync(0xffffffffu, v, o);
    return v;
}
__device__ __forceinline__ uint32_t smem_u32(const void* p) {
    uint32_t a;
    asm("{ .reg .u64 t; cvta.to.shared.u64 t, %1; cvt.u32.u64 %0, t; }" : "=r"(a) : "l"(p));
    return a;
}
__device__ __forceinline__ void ldsm4(uint32_t* r, uint32_t addr) {
    asm volatile("ldmatrix.sync.aligned.m8n8.x4.shared.b16 {%0,%1,%2,%3}, [%4];"
                 : "=r"(r[0]), "=r"(r[1]), "=r"(r[2]), "=r"(r[3]) : "r"(addr));
}
__device__ __forceinline__ void mma16816(float* d, const uint32_t* a, const uint32_t* b) {
    asm volatile("mma.sync.aligned.m16n8k16.row.col.f32.bf16.bf16.f32 "
                 "{%0,%1,%2,%3}, {%4,%5,%6,%7}, {%8,%9}, {%0,%1,%2,%3};"
                 : "+f"(d[0]), "+f"(d[1]), "+f"(d[2]), "+f"(d[3])
                 : "r"(a[0]), "r"(a[1]), "r"(a[2]), "r"(a[3]), "r"(b[0]), "r"(b[1]));
}
__device__ __forceinline__ void cp16(uint32_t dst, const uint4* src) {
    unsigned long long ga = (unsigned long long)__cvta_generic_to_global((const void*)src);
    asm volatile("cp.async.cg.shared.global [%0], [%1], 16;" :: "r"(dst), "l"(ga));
}
#define CP_COMMIT() asm volatile("cp.async.commit_group;" ::: "memory")
#define CP_WAIT(n)  asm volatile("cp.async.wait_group %0;" :: "n"(n) : "memory")

// packed f32 pair -> bf16x2 (lo = a, hi = b)
__device__ __forceinline__ uint32_t cvt_bf16x2(float a, float b) {
    uint32_t r;
    asm("cvt.rn.bf16x2.f32 %0, %1, %2;" : "=r"(r) : "f"(b), "f"(a));
    return r;
}

// ---------------------------------------------------------------------------
// Kernel 0: split W1 (= sel_w1 rows 0..255, [K=256][N=256]) into bf16 hi/lo,
// transposed to [N][K], stored as 8 swizzled 32KB SMEM chunk images.
// ---------------------------------------------------------------------------
__global__ __launch_bounds__(256) void k_wsplit(const float* __restrict__ W1) {
    int idx = blockIdx.x * 256 + threadIdx.x;   // 0..16383
    int c   = idx >> 11;
    int rem = idx & 2047;
    int n   = rem >> 3;
    int u   = rem & 7;
    int k0  = (c & 3) * 64 + u * 8;
    unsigned short us[8];
#pragma unroll
    for (int j = 0; j < 8; j++) {
        float wv = W1[(size_t)(k0 + j) * 256 + n];
        __nv_bfloat16 hb = __float2bfloat16(wv);
        if (c >= 4) hb = __float2bfloat16(wv - __bfloat162float(hb));
        us[j] = __bfloat16_as_ushort(hb);
    }
    uint4 out;
    out.x = (unsigned)us[0] | ((unsigned)us[1] << 16);
    out.y = (unsigned)us[2] | ((unsigned)us[3] << 16);
    out.z = (unsigned)us[4] | ((unsigned)us[5] << 16);
    out.w = (unsigned)us[6] | ((unsigned)us[7] << 16);
    g_wchunks[c*2048 + n*8 + (u ^ (n & 7))] = out;
}

// ---------------------------------------------------------------------------
// Kernel 1: per-batch MLPs. grid (128, 2): y=0 mu path, y=1 sigma+qpart+rsig.
// ---------------------------------------------------------------------------
template<int N>
__device__ __forceinline__ float dotT(const float* __restrict__ v,
                                      const float* __restrict__ w,
                                      int stride, int j) {
    float a0 = 0.f, a1 = 0.f, a2 = 0.f, a3 = 0.f;
#pragma unroll 16
    for (int d = 0; d < N; d += 4) {
        a0 = fmaf(v[d+0], __ldg(w + (size_t)(d+0)*stride + j), a0);
        a1 = fmaf(v[d+1], __ldg(w + (size_t)(d+1)*stride + j), a1);
        a2 = fmaf(v[d+2], __ldg(w + (size_t)(d+2)*stride + j), a2);
        a3 = fmaf(v[d+3], __ldg(w + (size_t)(d+3)*stride + j), a3);
    }
    return (a0 + a1) + (a2 + a3);
}

__global__ __launch_bounds__(256) void k_params(
    const float* __restrict__ qe,
    const float* __restrict__ mu_w1, const float* __restrict__ mu_b1,
    const float* __restrict__ mu_w2, const float* __restrict__ mu_b2,
    const float* __restrict__ ln_g,  const float* __restrict__ ln_b,
    const float* __restrict__ sg_w1, const float* __restrict__ sg_b1,
    const float* __restrict__ sg_w2, const float* __restrict__ sg_b2,
    const float* __restrict__ sel_w1,const float* __restrict__ sel_b1,
    float* __restrict__ out_mu, float* __restrict__ out_sig)
{
    __shared__ float q[256];
    __shared__ float h[512];
    __shared__ float red[8];
    int b = blockIdx.x, tid = threadIdx.x;
    int lane = tid & 31, wid = tid >> 5;

    q[tid] = qe[b*256 + tid];
    __syncthreads();

    if (blockIdx.y == 0) {
#pragma unroll
        for (int jj = 0; jj < 2; jj++) {
            int j = tid + jj*256;
            h[j] = gelu_f(dotT<256>(q, mu_w1, 512, j) + mu_b1[j]);
        }
        __syncthreads();
        float u = dotT<512>(h, mu_w2, 256, tid) + mu_b2[tid];

        float s = warpSum(u);
        if (lane == 0) red[wid] = s;
        __syncthreads();
        if (tid == 0) { float t = 0; for (int w = 0; w < 8; w++) t += red[w]; red[0] = t; }
        __syncthreads();
        float mean = red[0] * (1.0f/256.0f);
        __syncthreads();
        float df = u - mean;
        float s2 = warpSum(df*df);
        if (lane == 0) red[wid] = s2;
        __syncthreads();
        if (tid == 0) { float t = 0; for (int w = 0; w < 8; w++) t += red[w]; red[0] = t; }
        __syncthreads();
        float var = red[0] * (1.0f/256.0f);
        out_mu[b*256 + tid] = df * rsqrtf(var + 1e-5f) * ln_g[tid] + ln_b[tid];
    } else {
        h[tid] = gelu_f(dotT<256>(q, sg_w1, 256, tid) + sg_b1[tid]);
        __syncthreads();
        float o = dotT<256>(h, sg_w2, 256, tid) + sg_b2[tid];
        float sv = 1.0f/(1.0f + expf(-o)) * 2.0f + 0.1f;
        out_sig[b*256 + tid] = sv;
        g_rsig[b*256 + tid] = 1.0f / (sv + 1e-8f);
        g_qpart[b*256 + tid] = dotT<256>(q, sel_w1 + 65536, 256, tid) + sel_b1[tid];
    }
}

// ---------------------------------------------------------------------------
// Kernel 2: fused x/dist + mma.sync bf16 split GEMM + gelu@w2 epilogue.
//   Grid 4000 = 2000 row-tiles (64 rows) x 2 N-passes. 256 threads, occ 1.
//   SMEM: Ah 32K | Al 32K | B-half fully resident 128K = 192K.
//   B issued via cp.async BEFORE phase 1; ONE barrier; then the whole
//   8-chunk dual-A walk runs with zero synchronization.
//   Warp grid 2(M) x 4(N), warp tile 32x32, acc[2][4][4]=32 regs.
// ---------------------------------------------------------------------------
__device__ __forceinline__ void gemm_chunk_dual(float (&acc)[2][4][4],
    uint32_t ah, uint32_t al, uint32_t bbase, int kub, bool do_lo,
    int wm, int wn, int l)
{
    int lm = ((l >> 3) & 1) * 8 + (l & 7);
    int lu = l >> 4;
#pragma unroll
    for (int s = 0; s < 4; s++) {
        uint32_t bf[2][4];
#pragma unroll
        for (int ng = 0; ng < 2; ng++) {
            int n = wn*32 + ng*16 + lm;   // 0..127 within the N-half
            unsigned u = (unsigned)(s*2 + lu);
            uint32_t bd = bbase + (unsigned)n*128u +
                (((u ^ (unsigned)(n & 7)) & 7u) << 4);
            ldsm4(bf[ng], bd);
        }
        unsigned uk = (unsigned)(kub + s*2 + lu);
        uint32_t af[2][4];
#pragma unroll
        for (int mf = 0; mf < 2; mf++) {
            int m = wm*32 + mf*16 + lm;
            uint32_t ad = ah + (unsigned)m*512u +
                (((uk & ~7u) | ((uk ^ (unsigned)(m & 7)) & 7u)) << 4);
            ldsm4(af[mf], ad);
        }
#pragma unroll
        for (int mf = 0; mf < 2; mf++)
#pragma unroll
            for (int ng = 0; ng < 2; ng++) {
                uint32_t b0[2] = {bf[ng][0], bf[ng][2]};
                uint32_t b1[2] = {bf[ng][1], bf[ng][3]};
                mma16816(acc[mf][ng*2],     af[mf], b0);
                mma16816(acc[mf][ng*2 + 1], af[mf], b1);
            }
        if (do_lo) {
            uint32_t afl[2][4];
#pragma unroll
            for (int mf = 0; mf < 2; mf++) {
                int m = wm*32 + mf*16 + lm;
                uint32_t ad = al + (unsigned)m*512u +
                    (((uk & ~7u) | ((uk ^ (unsigned)(m & 7)) & 7u)) << 4);
                ldsm4(afl[mf], ad);
            }
#pragma unroll
            for (int mf = 0; mf < 2; mf++)
#pragma unroll
                for (int ng = 0; ng < 2; ng++) {
                    uint32_t b0[2] = {bf[ng][0], bf[ng][2]};
                    uint32_t b1[2] = {bf[ng][1], bf[ng][3]};
                    mma16816(acc[mf][ng*2],     afl[mf], b0);
                    mma16816(acc[mf][ng*2 + 1], afl[mf], b1);
                }
        }
    }
}

__global__ __launch_bounds__(256, 1) void k_rel(
    const float* __restrict__ vf, const float* __restrict__ pos,
    const float* __restrict__ mu, const float* __restrict__ w2,
    float* __restrict__ x_out, float* __restrict__ dist_out)
{
    extern __shared__ __align__(1024) char dsm[];

    int tid = threadIdx.x, w = tid >> 5, l = tid & 31;
    int wm = w >> 2, wn = w & 3;
    int bid = blockIdx.x;
    int tile = bid >> 1, pass = bid & 1;
    int row0 = tile * 64;
    int b0 = row0 / T_;
    int bsplit = (b0 + 1) * T_;
    int b1 = (row0 + 63) / T_;

    uint32_t dsm32 = smem_u32(dsm);
    uint32_t Ah = dsm32, Al = dsm32 + 32768u, Bb = dsm32 + 65536u;

    // Issue the ENTIRE B half (128KB, 8 chunks of 16KB) before phase 1.
#pragma unroll
    for (int c = 0; c < 8; c++)
#pragma unroll
        for (int i = 0; i < 4; i++)
            cp16(Bb + (unsigned)c*16384u + (unsigned)(tid + i*256)*16u,
                 g_wchunks + c*2048 + pass*1024 + tid + i*256);
    CP_COMMIT();

    // ---- phase 1: x = vf+pos, dist (pass 0 only writes), split-bf16 A ----
    {
        int r = tid >> 2, q = tid & 3;    // 64 rows x 4 col-groups
        int grow = row0 + r;
        int bq = grow / T_;
        int tq = grow - bq * T_;
        const float4* vp = (const float4*)(vf  + (size_t)grow*256 + q*64);
        const float4* pp = (const float4*)(pos + (size_t)tq  *256 + q*64);
        const float4* mp = (const float4*)(mu  + bq*256 + q*64);
        const float4* rp = (const float4*)(g_rsig + bq*256 + q*64);
        float4* xo = (float4*)(x_out + (size_t)grow*256 + q*64);
        float dsum = 0.f;
#pragma unroll 4
        for (int g = 0; g < 16; g++) {
            float4 v = vp[g], p = pp[g], m = mp[g], rs = rp[g];
            float4 xq;
            xq.x = v.x + p.x; xq.y = v.y + p.y; xq.z = v.z + p.z; xq.w = v.w + p.w;
            if (pass == 0) xo[g] = xq;
            float c;
            c = xq.x - m.x; dsum = fmaf(c*c, rs.x, dsum);
            c = xq.y - m.y; dsum = fmaf(c*c, rs.y, dsum);
            c = xq.z - m.z; dsum = fmaf(c*c, rs.z, dsum);
            c = xq.w - m.w; dsum = fmaf(c*c, rs.w, dsum);
            uint32_t h01 = cvt_bf16x2(xq.x, xq.y);
            uint32_t h23 = cvt_bf16x2(xq.z, xq.w);
            float f0 = __uint_as_float(h01 << 16);
            float f1 = __uint_as_float(h01 & 0xFFFF0000u);
            float f2 = __uint_as_float(h23 << 16);
            float f3 = __uint_as_float(h23 & 0xFFFF0000u);
            uint32_t l01 = cvt_bf16x2(xq.x - f0, xq.y - f1);
            uint32_t l23 = cvt_bf16x2(xq.z - f2, xq.w - f3);
            int col = q*64 + g*4;
            unsigned u = (unsigned)(col >> 3);
            unsigned phys = (u & ~7u) | ((u ^ (unsigned)(r & 7)) & 7u);
            unsigned off = (unsigned)r*512u + (phys << 4) + ((unsigned)(col & 7)) * 2u;
            *(uint2*)(dsm + off)          = make_uint2(h01, h23);
            *(uint2*)(dsm + 32768u + off) = make_uint2(l01, l23);
        }
        dsum += __shfl_xor_sync(0xffffffffu, dsum, 1);
        dsum += __shfl_xor_sync(0xffffffffu, dsum, 2);
        if (q == 0 && pass == 0) dist_out[grow] = fmaxf(dsum, 1e-8f);
    }

    float acc[2][4][4];
#pragma unroll
    for (int mf = 0; mf < 2; mf++)
#pragma unroll
        for (int nf = 0; nf < 4; nf++)
#pragma unroll
            for (int i = 0; i < 4; i++) acc[mf][nf][i] = 0.f;

    CP_WAIT(0);
    __syncthreads();   // the ONLY barrier before the walk

    // ---- 8-chunk dual-A walk: no syncs, B fully resident ----
#pragma unroll
    for (int bc = 0; bc < 8; bc++)
        gemm_chunk_dual(acc, Ah, Al, Bb + (unsigned)bc*16384u,
                        (bc & 3) * 8, bc < 4, wm, wn, l);

    // ---- epilogue: partial rel for this N-half ----
    const float* qp0 = g_qpart + b0*256;
    const float* qp1 = g_qpart + b1*256;
    int colbase = pass*128 + wn*32;
    float s_acc[2][2];
#pragma unroll
    for (int mf = 0; mf < 2; mf++) {
        int R0 = wm*32 + mf*16 + (l >> 2);
        const float* qpA = (row0 + R0 >= bsplit) ? qp1 : qp0;
        const float* qpB = (row0 + R0 + 8 >= bsplit) ? qp1 : qp0;
        float s0 = 0.f, s1 = 0.f;
#pragma unroll
        for (int nf = 0; nf < 4; nf++) {
            int col0 = colbase + nf*8 + 2*(l & 3);
            int col1 = col0 + 1;
            const float* a = acc[mf][nf];
            float wa = __ldg(w2 + col0);
            float wb = __ldg(w2 + col1);
            s0 = fmaf(gelu_f(a[0] + __ldg(qpA + col0)), wa, s0);
            s0 = fmaf(gelu_f(a[1] + __ldg(qpA + col1)), wb, s0);
            s1 = fmaf(gelu_f(a[2] + __ldg(qpB + col0)), wa, s1);
            s1 = fmaf(gelu_f(a[3] + __ldg(qpB + col1)), wb, s1);
        }
        s_acc[mf][0] = s0;
        s_acc[mf][1] = s1;
    }
    __syncthreads();   // all warps done with B region before reuse as sred

    float* sred = (float*)(dsm + 65536);   // [64][4]
#pragma unroll
    for (int mf = 0; mf < 2; mf++) {
        int R0 = wm*32 + mf*16 + (l >> 2);
        int R1 = R0 + 8;
        float s0 = s_acc[mf][0], s1 = s_acc[mf][1];
        s0 += __shfl_xor_sync(0xffffffffu, s0, 1);
        s0 += __shfl_xor_sync(0xffffffffu, s0, 2);
        s1 += __shfl_xor_sync(0xffffffffu, s1, 1);
        s1 += __shfl_xor_sync(0xffffffffu, s1, 2);
        if ((l & 3) == 0) {
            sred[R0*4 + wn] = s0;
            sred[R1*4 + wn] = s1;
        }
    }
    __syncthreads();
    if (tid < 64) {
        g_relp[pass][row0 + tid] = sred[tid*4 + 0] + sred[tid*4 + 1]
                                 + sred[tid*4 + 2] + sred[tid*4 + 3];
    }
}

// ---------------------------------------------------------------------------
// Kernel 3: per-batch median (radix select), comb, top-12, diversify, gather.
// rel = g_relp[0] + g_relp[1] + b2 (deterministic two-part sum).
// ---------------------------------------------------------------------------
__global__ __launch_bounds__(256) void k_select(
    const float* __restrict__ dist, const float* __restrict__ x,
    const float* __restrict__ b2p,
    float* __restrict__ out_rep, float* __restrict__ out_idx)
{
    __shared__ float sdist[T_];
    __shared__ float scomb[1024];
    __shared__ int   hist[256];
    __shared__ unsigned s_prefix;
    __shared__ int   s_rank;
    __shared__ float s_wv[8];
    __shared__ int   s_wi[8];
    __shared__ int   s_cand[12];
    __shared__ int   s_sel[6];

    int b = blockIdx.x, tid = threadIdx.x;
    int lane = tid & 31, wid = tid >> 5;

    for (int i = tid; i < T_; i += 256) sdist[i] = dist[b*T_ + i];
    __syncthreads();

    // median = sorted[499]: 4-round radix select on positive-float bits
    unsigned prefix = 0;
    int rank = 499;
    for (int shift = 24; shift >= 0; shift -= 8) {
        hist[tid] = 0;
        __syncthreads();
        unsigned hmask = (shift == 24) ? 0u : (0xFFFFFFFFu << (shift + 8));
        for (int i = tid; i < T_; i += 256) {
            unsigned v = __float_as_uint(sdist[i]);
            if ((v & hmask) == prefix)
                atomicAdd(&hist[(v >> shift) & 255], 1);
        }
        __syncthreads();
        if (tid == 0) {
            int cum = 0, bk = 0;
            for (; bk < 256; bk++) {
                int h = hist[bk];
                if (cum + h > rank) break;
                cum += h;
            }
            s_prefix = prefix | ((unsigned)bk << shift);
            s_rank = rank - cum;
        }
        __syncthreads();
        prefix = s_prefix;
        rank = s_rank;
        __syncthreads();
    }
    float med = __uint_as_float(prefix);
    float b2 = __ldg(b2p);

    for (int i = tid; i < 1024; i += 256) {
        if (i < T_) {
            float rel = g_relp[0][b*T_ + i] + g_relp[1][b*T_ + i] + b2;
            scomb[i] = -fabsf(sdist[i] - med) + 0.5f * rel;
        } else {
            scomb[i] = -FLT_MAX;
        }
    }
    __syncthreads();

    for (int it = 0; it < 12; it++) {
        float bv = -FLT_MAX; int bi = 1023;
        for (int i = tid; i < 1024; i += 256) {
            float v = scomb[i];
            if (v > bv) { bv = v; bi = i; }
        }
#pragma unroll
        for (int o = 16; o > 0; o >>= 1) {
            float ov = __shfl_down_sync(0xffffffffu, bv, o);
            int   oi = __shfl_down_sync(0xffffffffu, bi, o);
            if (ov > bv || (ov == bv && oi < bi)) { bv = ov; bi = oi; }
        }
        if (lane == 0) { s_wv[wid] = bv; s_wi[wid] = bi; }
        __syncthreads();
        if (tid == 0) {
            float Bv = s_wv[0]; int Bi = s_wi[0];
            for (int ww = 1; ww < 8; ww++)
                if (s_wv[ww] > Bv || (s_wv[ww] == Bv && s_wi[ww] < Bi)) { Bv = s_wv[ww]; Bi = s_wi[ww]; }
            s_cand[it] = Bi;
            scomb[Bi] = -FLT_MAX;
        }
        __syncthreads();
    }

    if (tid == 0) {
        int c[12];
        for (int i = 0; i < 12; i++) c[i] = s_cand[i];
        for (int i = 1; i < 12; i++) {
            int key = c[i], j = i - 1;
            while (j >= 0 && c[j] > key) { c[j+1] = c[j]; j--; }
            c[j+1] = key;
        }
        int md[12]; bool rem[12];
        for (int i = 0; i < 12; i++) { md[i] = abs(c[i] - c[0]); rem[i] = (i != 0); }
        s_sel[0] = c[0];
        for (int s = 1; s < 6; s++) {
            int best = -2, bi = 0;
            for (int i = 0; i < 12; i++) {
                int sc = rem[i] ? md[i] : -1;
                if (sc > best) { best = sc; bi = i; }
            }
            int sv = c[bi]; rem[bi] = false;
            for (int i = 0; i < 12; i++) { int dd = abs(c[i] - sv); if (dd < md[i]) md[i] = dd; }
            s_sel[s] = sv;
        }
        for (int k = 0; k < 6; k++) out_idx[b*6 + k] = (float)s_sel[k];
    }
    __syncthreads();

    for (int i = tid; i < 6*256; i += 256) {
        int k = i >> 8, d = i & 255;
        out_rep[((size_t)b*6 + k)*256 + d] = x[((size_t)b*T_ + s_sel[k])*256 + d];
    }
}

// ---------------------------------------------------------------------------
extern "C" void kernel_launch(void* const* d_in, const int* in_sizes, int n_in,
                              void* d_out, int out_size)
{
    const float* vf    = (const float*)d_in[0];
    const float* qe    = (const float*)d_in[1];
    const float* pos   = (const float*)d_in[2];
    const float* mu_w1 = (const float*)d_in[3];
    const float* mu_b1 = (const float*)d_in[4];
    const float* mu_w2 = (const float*)d_in[5];
    const float* mu_b2 = (const float*)d_in[6];
    const float* ln_g  = (const float*)d_in[7];
    const float* ln_b  = (const float*)d_in[8];
    const float* sg_w1 = (const float*)d_in[9];
    const float* sg_b1 = (const float*)d_in[10];
    const float* sg_w2 = (const float*)d_in[11];
    const float* sg_b2 = (const float*)d_in[12];
    const float* sel_w1= (const float*)d_in[13];
    const float* sel_b1= (const float*)d_in[14];
    const float* sel_w2= (const float*)d_in[15];
    const float* sel_b2= (const float*)d_in[16];

    float* out      = (float*)d_out;
    float* out_rep  = out;               // [128,6,256]
    float* out_idx  = out + 196608;      // [128,6]
    float* out_dist = out + 197376;      // [128,1000]
    float* out_mu   = out + 325376;      // [128,256]
    float* out_sig  = out + 358144;      // [128,256]
    float* out_x    = out + 390912;      // [128,1000,256]

    static int s_attr_done = 0;
    if (!s_attr_done) {
        cudaFuncSetAttribute(k_rel, cudaFuncAttributeMaxDynamicSharedMemorySize, 196608);
        s_attr_done = 1;
    }

    k_wsplit<<<64, 256>>>(sel_w1);
    k_params<<<dim3(B_, 2), 256>>>(qe, mu_w1, mu_b1, mu_w2, mu_b2, ln_g, ln_b,
                                   sg_w1, sg_b1, sg_w2, sg_b2, sel_w1, sel_b1,
                                   out_mu, out_sig);
    k_rel<<<4000, 256, 196608>>>(vf, pos, out_mu, sel_w2, out_x, out_dist);
    k_select<<<B_, 256>>>(out_dist, out_x, sel_b2, out_rep, out_idx);
}

// round 16
// speedup vs baseline: 1.3535x; 1.3535x over previous
#include <cuda_runtime.h>
#include <cuda_bf16.h>
#include <math.h>
#include <float.h>
#include <stdint.h>

#define B_   128
#define T_   1000
#define ROWS_ (B_*T_)

// ---------------- device scratch (no allocs allowed) ----------------
__device__ float g_qpart[B_*256];
__device__ float g_rsig[B_*256];
__device__ float g_rel[ROWS_];
__device__ uint4 g_wchunks[8*2048];   // 8 chunks x 32KB swizzled SMEM images of Wh/Wl, [n][k] layout

// ---------------- helpers ----------------
__device__ __forceinline__ float gelu_f(float v) {
    return 0.5f * v * (1.0f + erff(v * 0.7071067811865475f));
}
__device__ __forceinline__ float warpSum(float v) {
#pragma unroll
    for (int o = 16; o > 0; o >>= 1) v += __shfl_down_sync(0xffffffffu, v, o);
    return v;
}
__device__ __forceinline__ uint32_t smem_u32(const void* p) {
    uint32_t a;
    asm("{ .reg .u64 t; cvta.to.shared.u64 t, %1; cvt.u32.u64 %0, t; }" : "=r"(a) : "l"(p));
    return a;
}
__device__ __forceinline__ void ldsm4(uint32_t* r, uint32_t addr) {
    asm volatile("ldmatrix.sync.aligned.m8n8.x4.shared.b16 {%0,%1,%2,%3}, [%4];"
                 : "=r"(r[0]), "=r"(r[1]), "=r"(r[2]), "=r"(r[3]) : "r"(addr));
}
__device__ __forceinline__ void mma16816(float* d, const uint32_t* a, const uint32_t* b) {
    asm volatile("mma.sync.aligned.m16n8k16.row.col.f32.bf16.bf16.f32 "
                 "{%0,%1,%2,%3}, {%4,%5,%6,%7}, {%8,%9}, {%0,%1,%2,%3};"
                 : "+f"(d[0]), "+f"(d[1]), "+f"(d[2]), "+f"(d[3])
                 : "r"(a[0]), "r"(a[1]), "r"(a[2]), "r"(a[3]), "r"(b[0]), "r"(b[1]));
}
__device__ __forceinline__ void cp16(uint32_t dst, const uint4* src) {
    unsigned long long ga = (unsigned long long)__cvta_generic_to_global((const void*)src);
    asm volatile("cp.async.cg.shared.global [%0], [%1], 16;" :: "r"(dst), "l"(ga));
}
#define CP_COMMIT() asm volatile("cp.async.commit_group;" ::: "memory")
#define CP_WAIT(n)  asm volatile("cp.async.wait_group %0;" :: "n"(n) : "memory")

// packed f32 pair -> bf16x2 (lo = a, hi = b)
__device__ __forceinline__ uint32_t cvt_bf16x2(float a, float b) {
    uint32_t r;
    asm("cvt.rn.bf16x2.f32 %0, %1, %2;" : "=r"(r) : "f"(b), "f"(a));
    return r;
}

// ---------------------------------------------------------------------------
// Kernel 0: split W1 (= sel_w1 rows 0..255, [K=256][N=256]) into bf16 hi/lo,
// transposed to [N][K], stored as 8 swizzled 32KB SMEM chunk images.
// ---------------------------------------------------------------------------
__global__ __launch_bounds__(256) void k_wsplit(const float* __restrict__ W1) {
    int idx = blockIdx.x * 256 + threadIdx.x;   // 0..16383
    int c   = idx >> 11;
    int rem = idx & 2047;
    int n   = rem >> 3;
    int u   = rem & 7;
    int k0  = (c & 3) * 64 + u * 8;
    unsigned short us[8];
#pragma unroll
    for (int j = 0; j < 8; j++) {
        float wv = W1[(size_t)(k0 + j) * 256 + n];
        __nv_bfloat16 hb = __float2bfloat16(wv);
        if (c >= 4) hb = __float2bfloat16(wv - __bfloat162float(hb));
        us[j] = __bfloat16_as_ushort(hb);
    }
    uint4 out;
    out.x = (unsigned)us[0] | ((unsigned)us[1] << 16);
    out.y = (unsigned)us[2] | ((unsigned)us[3] << 16);
    out.z = (unsigned)us[4] | ((unsigned)us[5] << 16);
    out.w = (unsigned)us[6] | ((unsigned)us[7] << 16);
    g_wchunks[c*2048 + n*8 + (u ^ (n & 7))] = out;
}

// ---------------------------------------------------------------------------
// Kernel 1: per-batch MLPs. grid (128, 2): y=0 mu path, y=1 sigma+qpart+rsig.
// ---------------------------------------------------------------------------
template<int N>
__device__ __forceinline__ float dotT(const float* __restrict__ v,
                                      const float* __restrict__ w,
                                      int stride, int j) {
    float a0 = 0.f, a1 = 0.f, a2 = 0.f, a3 = 0.f;
#pragma unroll 16
    for (int d = 0; d < N; d += 4) {
        a0 = fmaf(v[d+0], __ldg(w + (size_t)(d+0)*stride + j), a0);
        a1 = fmaf(v[d+1], __ldg(w + (size_t)(d+1)*stride + j), a1);
        a2 = fmaf(v[d+2], __ldg(w + (size_t)(d+2)*stride + j), a2);
        a3 = fmaf(v[d+3], __ldg(w + (size_t)(d+3)*stride + j), a3);
    }
    return (a0 + a1) + (a2 + a3);
}

__global__ __launch_bounds__(256) void k_params(
    const float* __restrict__ qe,
    const float* __restrict__ mu_w1, const float* __restrict__ mu_b1,
    const float* __restrict__ mu_w2, const float* __restrict__ mu_b2,
    const float* __restrict__ ln_g,  const float* __restrict__ ln_b,
    const float* __restrict__ sg_w1, const float* __restrict__ sg_b1,
    const float* __restrict__ sg_w2, const float* __restrict__ sg_b2,
    const float* __restrict__ sel_w1,const float* __restrict__ sel_b1,
    float* __restrict__ out_mu, float* __restrict__ out_sig)
{
    __shared__ float q[256];
    __shared__ float h[512];
    __shared__ float red[8];
    int b = blockIdx.x, tid = threadIdx.x;
    int lane = tid & 31, wid = tid >> 5;

    q[tid] = qe[b*256 + tid];
    __syncthreads();

    if (blockIdx.y == 0) {
#pragma unroll
        for (int jj = 0; jj < 2; jj++) {
            int j = tid + jj*256;
            h[j] = gelu_f(dotT<256>(q, mu_w1, 512, j) + mu_b1[j]);
        }
        __syncthreads();
        float u = dotT<512>(h, mu_w2, 256, tid) + mu_b2[tid];

        float s = warpSum(u);
        if (lane == 0) red[wid] = s;
        __syncthreads();
        if (tid == 0) { float t = 0; for (int w = 0; w < 8; w++) t += red[w]; red[0] = t; }
        __syncthreads();
        float mean = red[0] * (1.0f/256.0f);
        __syncthreads();
        float df = u - mean;
        float s2 = warpSum(df*df);
        if (lane == 0) red[wid] = s2;
        __syncthreads();
        if (tid == 0) { float t = 0; for (int w = 0; w < 8; w++) t += red[w]; red[0] = t; }
        __syncthreads();
        float var = red[0] * (1.0f/256.0f);
        out_mu[b*256 + tid] = df * rsqrtf(var + 1e-5f) * ln_g[tid] + ln_b[tid];
    } else {
        h[tid] = gelu_f(dotT<256>(q, sg_w1, 256, tid) + sg_b1[tid]);
        __syncthreads();
        float o = dotT<256>(h, sg_w2, 256, tid) + sg_b2[tid];
        float sv = 1.0f/(1.0f + expf(-o)) * 2.0f + 0.1f;
        out_sig[b*256 + tid] = sv;
        g_rsig[b*256 + tid] = 1.0f / (sv + 1e-8f);
        g_qpart[b*256 + tid] = dotT<256>(q, sel_w1 + 65536, 256, tid) + sel_b1[tid];
    }
}

// ---------------------------------------------------------------------------
// Kernel 2: fused x/dist + mma.sync bf16 split GEMM + gelu@w2 epilogue.
//   SINGLE launch: 1000 blocks x 256 threads, occ 1. Tile: 128 rows,
//   N=256 in two 128-col passes. Warp grid 4(M) x 2(N), warp tile 32x64,
//   acc[2][8][4]=64 regs. Dual-A chunks: B frags loaded ONCE per k-step,
//   shared by Xh and Xl MMAs. SMEM: Ah 64K | Al 64K | B triple 3x16K = 176K.
// ---------------------------------------------------------------------------
__device__ __forceinline__ void gemm_chunk_dual(float (&acc)[2][8][4],
    uint32_t ah, uint32_t al, uint32_t bbase, int kub, bool do_lo,
    int wm, int wn, int l)
{
    int lm = ((l >> 3) & 1) * 8 + (l & 7);
    int lu = l >> 4;
#pragma unroll
    for (int s = 0; s < 4; s++) {
        uint32_t bf[4][4];
#pragma unroll
        for (int ng = 0; ng < 4; ng++) {
            int n = wn*64 + ng*16 + lm;
            unsigned u = (unsigned)(s*2 + lu);
            uint32_t bd = bbase + (unsigned)n*128u +
                (((u ^ (unsigned)(n & 7)) & 7u) << 4);
            ldsm4(bf[ng], bd);
        }
        unsigned uk = (unsigned)(kub + s*2 + lu);
        uint32_t af[2][4];
#pragma unroll
        for (int mf = 0; mf < 2; mf++) {
            int m = wm*32 + mf*16 + lm;
            uint32_t ad = ah + (unsigned)m*512u +
                (((uk & ~7u) | ((uk ^ (unsigned)(m & 7)) & 7u)) << 4);
            ldsm4(af[mf], ad);
        }
#pragma unroll
        for (int mf = 0; mf < 2; mf++)
#pragma unroll
            for (int ng = 0; ng < 4; ng++) {
                uint32_t b0[2] = {bf[ng][0], bf[ng][2]};
                uint32_t b1[2] = {bf[ng][1], bf[ng][3]};
                mma16816(acc[mf][ng*2],     af[mf], b0);
                mma16816(acc[mf][ng*2 + 1], af[mf], b1);
            }
        if (do_lo) {
            uint32_t afl[2][4];
#pragma unroll
            for (int mf = 0; mf < 2; mf++) {
                int m = wm*32 + mf*16 + lm;
                uint32_t ad = al + (unsigned)m*512u +
                    (((uk & ~7u) | ((uk ^ (unsigned)(m & 7)) & 7u)) << 4);
                ldsm4(afl[mf], ad);
            }
#pragma unroll
            for (int mf = 0; mf < 2; mf++)
#pragma unroll
                for (int ng = 0; ng < 4; ng++) {
                    uint32_t b0[2] = {bf[ng][0], bf[ng][2]};
                    uint32_t b1[2] = {bf[ng][1], bf[ng][3]};
                    mma16816(acc[mf][ng*2],     afl[mf], b0);
                    mma16816(acc[mf][ng*2 + 1], afl[mf], b1);
                }
        }
    }
}

__global__ __launch_bounds__(256, 1) void k_rel(
    const float* __restrict__ vf, const float* __restrict__ pos,
    const float* __restrict__ mu,
    const float* __restrict__ w2, const float* __restrict__ b2p,
    float* __restrict__ x_out, float* __restrict__ dist_out)
{
    extern __shared__ __align__(1024) char dsm[];

    int tid = threadIdx.x, w = tid >> 5, l = tid & 31;
    int wm = w >> 1, wn = w & 1;
    int row0 = blockIdx.x * 128;
    int b0 = row0 / T_;
    int bsplit = (b0 + 1) * T_;
    int b1 = (row0 + 127) / T_;

    uint32_t dsm32 = smem_u32(dsm);
    uint32_t bbuf[3] = { dsm32 + 131072u, dsm32 + 147456u, dsm32 + 163840u };

    // prefetch pass-0 B chunk-halves 0 and 1 before phase 1
#pragma unroll
    for (int i = 0; i < 4; i++)
        cp16(bbuf[0] + (unsigned)(tid + i*256)*16u, g_wchunks + tid + i*256);
    CP_COMMIT();
#pragma unroll
    for (int i = 0; i < 4; i++)
        cp16(bbuf[1] + (unsigned)(tid + i*256)*16u, g_wchunks + 2048 + tid + i*256);
    CP_COMMIT();

    // ---- phase 1: x = vf+pos (write), dist (write), split-bf16 A tile ----
    {
        int r = tid >> 1, q = tid & 1;    // 128 rows x 2 col-halves of 128
        int grow = row0 + r;
        int bq = grow / T_;
        int tq = grow - bq * T_;
        const float4* vp = (const float4*)(vf  + (size_t)grow*256 + q*128);
        const float4* pp = (const float4*)(pos + (size_t)tq  *256 + q*128);
        const float4* mp = (const float4*)(mu  + bq*256 + q*128);
        const float4* rp = (const float4*)(g_rsig + bq*256 + q*128);
        float4* xo = (float4*)(x_out + (size_t)grow*256 + q*128);
        float dsum = 0.f;
#pragma unroll 4
        for (int g = 0; g < 32; g++) {
            float4 v = vp[g], p = pp[g], m = mp[g], rs = rp[g];
            float4 xq;
            xq.x = v.x + p.x; xq.y = v.y + p.y; xq.z = v.z + p.z; xq.w = v.w + p.w;
            xo[g] = xq;
            float c;
            c = xq.x - m.x; dsum = fmaf(c*c, rs.x, dsum);
            c = xq.y - m.y; dsum = fmaf(c*c, rs.y, dsum);
            c = xq.z - m.z; dsum = fmaf(c*c, rs.z, dsum);
            c = xq.w - m.w; dsum = fmaf(c*c, rs.w, dsum);
            uint32_t h01 = cvt_bf16x2(xq.x, xq.y);
            uint32_t h23 = cvt_bf16x2(xq.z, xq.w);
            float f0 = __uint_as_float(h01 << 16);
            float f1 = __uint_as_float(h01 & 0xFFFF0000u);
            float f2 = __uint_as_float(h23 << 16);
            float f3 = __uint_as_float(h23 & 0xFFFF0000u);
            uint32_t l01 = cvt_bf16x2(xq.x - f0, xq.y - f1);
            uint32_t l23 = cvt_bf16x2(xq.z - f2, xq.w - f3);
            int col = q*128 + g*4;
            unsigned u = (unsigned)(col >> 3);
            unsigned phys = (u & ~7u) | ((u ^ (unsigned)(r & 7)) & 7u);
            unsigned off = (unsigned)r*512u + (phys << 4) + ((unsigned)(col & 7)) * 2u;
            *(uint2*)(dsm + off)         = make_uint2(h01, h23);
            *(uint2*)(dsm + 65536 + off) = make_uint2(l01, l23);
        }
        dsum += __shfl_xor_sync(0xffffffffu, dsum, 1);
        if (q == 0) dist_out[grow] = fmaxf(dsum, 1e-8f);
    }

    const float* qp0 = g_qpart + b0*256;
    const float* qp1 = g_qpart + b1*256;
    float s_acc[2][2] = {{0.f, 0.f}, {0.f, 0.f}};   // epilogue partials across passes

    for (int pass = 0; pass < 2; pass++) {
        if (pass == 1) {
            __syncthreads();   // all pass-0 gemm done before overwriting buffers
#pragma unroll
            for (int i = 0; i < 4; i++)
                cp16(bbuf[0] + (unsigned)(tid + i*256)*16u, g_wchunks + 1024 + tid + i*256);
            CP_COMMIT();
#pragma unroll
            for (int i = 0; i < 4; i++)
                cp16(bbuf[1] + (unsigned)(tid + i*256)*16u, g_wchunks + 2048 + 1024 + tid + i*256);
            CP_COMMIT();
        }

        float acc[2][8][4];
#pragma unroll
        for (int mf = 0; mf < 2; mf++)
#pragma unroll
            for (int nf = 0; nf < 8; nf++)
#pragma unroll
                for (int i = 0; i < 4; i++) acc[mf][nf][i] = 0.f;

        for (int bc = 0; bc < 8; bc++) {
            if (bc < 7) { CP_WAIT(1); } else { CP_WAIT(0); }
            __syncthreads();
            if (bc + 2 < 8) {
                const uint4* src = g_wchunks + (bc + 2) * 2048 + pass * 1024;
                uint32_t dst = bbuf[(bc + 2) % 3];
#pragma unroll
                for (int i = 0; i < 4; i++)
                    cp16(dst + (unsigned)(tid + i*256)*16u, src + tid + i*256);
                CP_COMMIT();
            }
            gemm_chunk_dual(acc, dsm32, dsm32 + 65536u, bbuf[bc % 3],
                            (bc & 3) * 8, bc < 4, wm, wn, l);
        }

        // epilogue partial for this N-half (registers only)
        int colbase = pass*128 + wn*64;
#pragma unroll
        for (int mf = 0; mf < 2; mf++) {
            int R0 = wm*32 + mf*16 + (l >> 2);
            const float* qpA = (row0 + R0 >= bsplit) ? qp1 : qp0;
            const float* qpB = (row0 + R0 + 8 >= bsplit) ? qp1 : qp0;
            float s0 = 0.f, s1 = 0.f;
#pragma unroll
            for (int nf = 0; nf < 8; nf++) {
                int col0 = colbase + nf*8 + 2*(l & 3);
                int col1 = col0 + 1;
                const float* a = acc[mf][nf];
                float wa = __ldg(w2 + col0);
                float wb = __ldg(w2 + col1);
                s0 = fmaf(gelu_f(a[0] + __ldg(qpA + col0)), wa, s0);
                s0 = fmaf(gelu_f(a[1] + __ldg(qpA + col1)), wb, s0);
                s1 = fmaf(gelu_f(a[2] + __ldg(qpB + col0)), wa, s1);
                s1 = fmaf(gelu_f(a[3] + __ldg(qpB + col1)), wb, s1);
            }
            s_acc[mf][0] += s0;
            s_acc[mf][1] += s1;
        }
    }
    __syncthreads();   // gemm/epilogue done before reusing B region as sred

    // ---- final reduction: shfl over lane quads, then across wn via smem ----
    float* sred = (float*)(dsm + 131072);   // [128][2]
#pragma unroll
    for (int mf = 0; mf < 2; mf++) {
        int R0 = wm*32 + mf*16 + (l >> 2);
        int R1 = R0 + 8;
        float s0 = s_acc[mf][0], s1 = s_acc[mf][1];
        s0 += __shfl_xor_sync(0xffffffffu, s0, 1);
        s0 += __shfl_xor_sync(0xffffffffu, s0, 2);
        s1 += __shfl_xor_sync(0xffffffffu, s1, 1);
        s1 += __shfl_xor_sync(0xffffffffu, s1, 2);
        if ((l & 3) == 0) {
            sred[R0*2 + wn] = s0;
            sred[R1*2 + wn] = s1;
        }
    }
    __syncthreads();
    if (tid < 128) {
        g_rel[row0 + tid] = sred[tid*2 + 0] + sred[tid*2 + 1] + __ldg(b2p);
    }
}

// ---------------------------------------------------------------------------
// Kernel 3: per-batch median (radix select), comb, top-12, diversify, gather.
// ---------------------------------------------------------------------------
__global__ __launch_bounds__(256) void k_select(
    const float* __restrict__ dist, const float* __restrict__ x,
    float* __restrict__ out_rep, float* __restrict__ out_idx)
{
    __shared__ float sdist[T_];
    __shared__ float scomb[1024];
    __shared__ int   hist[256];
    __shared__ unsigned s_prefix;
    __shared__ int   s_rank;
    __shared__ float s_wv[8];
    __shared__ int   s_wi[8];
    __shared__ int   s_cand[12];
    __shared__ int   s_sel[6];

    int b = blockIdx.x, tid = threadIdx.x;
    int lane = tid & 31, wid = tid >> 5;

    for (int i = tid; i < T_; i += 256) sdist[i] = dist[b*T_ + i];
    __syncthreads();

    // median = sorted[499]: 4-round radix select on positive-float bits
    unsigned prefix = 0;
    int rank = 499;
    for (int shift = 24; shift >= 0; shift -= 8) {
        hist[tid] = 0;
        __syncthreads();
        unsigned hmask = (shift == 24) ? 0u : (0xFFFFFFFFu << (shift + 8));
        for (int i = tid; i < T_; i += 256) {
            unsigned v = __float_as_uint(sdist[i]);
            if ((v & hmask) == prefix)
                atomicAdd(&hist[(v >> shift) & 255], 1);
        }
        __syncthreads();
        if (tid == 0) {
            int cum = 0, bk = 0;
            for (; bk < 256; bk++) {
                int h = hist[bk];
                if (cum + h > rank) break;
                cum += h;
            }
            s_prefix = prefix | ((unsigned)bk << shift);
            s_rank = rank - cum;
        }
        __syncthreads();
        prefix = s_prefix;
        rank = s_rank;
        __syncthreads();
    }
    float med = __uint_as_float(prefix);

    for (int i = tid; i < 1024; i += 256) {
        if (i < T_) scomb[i] = -fabsf(sdist[i] - med) + 0.5f * g_rel[b*T_ + i];
        else        scomb[i] = -FLT_MAX;
    }
    __syncthreads();

    for (int it = 0; it < 12; it++) {
        float bv = -FLT_MAX; int bi = 1023;
        for (int i = tid; i < 1024; i += 256) {
            float v = scomb[i];
            if (v > bv) { bv = v; bi = i; }
        }
#pragma unroll
        for (int o = 16; o > 0; o >>= 1) {
            float ov = __shfl_down_sync(0xffffffffu, bv, o);
            int   oi = __shfl_down_sync(0xffffffffu, bi, o);
            if (ov > bv || (ov == bv && oi < bi)) { bv = ov; bi = oi; }
        }
        if (lane == 0) { s_wv[wid] = bv; s_wi[wid] = bi; }
        __syncthreads();
        if (tid == 0) {
            float Bv = s_wv[0]; int Bi = s_wi[0];
            for (int ww = 1; ww < 8; ww++)
                if (s_wv[ww] > Bv || (s_wv[ww] == Bv && s_wi[ww] < Bi)) { Bv = s_wv[ww]; Bi = s_wi[ww]; }
            s_cand[it] = Bi;
            scomb[Bi] = -FLT_MAX;
        }
        __syncthreads();
    }

    if (tid == 0) {
        int c[12];
        for (int i = 0; i < 12; i++) c[i] = s_cand[i];
        for (int i = 1; i < 12; i++) {
            int key = c[i], j = i - 1;
            while (j >= 0 && c[j] > key) { c[j+1] = c[j]; j--; }
            c[j+1] = key;
        }
        int md[12]; bool rem[12];
        for (int i = 0; i < 12; i++) { md[i] = abs(c[i] - c[0]); rem[i] = (i != 0); }
        s_sel[0] = c[0];
        for (int s = 1; s < 6; s++) {
            int best = -2, bi = 0;
            for (int i = 0; i < 12; i++) {
                int sc = rem[i] ? md[i] : -1;
                if (sc > best) { best = sc; bi = i; }
            }
            int sv = c[bi]; rem[bi] = false;
            for (int i = 0; i < 12; i++) { int dd = abs(c[i] - sv); if (dd < md[i]) md[i] = dd; }
            s_sel[s] = sv;
        }
        for (int k = 0; k < 6; k++) out_idx[b*6 + k] = (float)s_sel[k];
    }
    __syncthreads();

    for (int i = tid; i < 6*256; i += 256) {
        int k = i >> 8, d = i & 255;
        out_rep[((size_t)b*6 + k)*256 + d] = x[((size_t)b*T_ + s_sel[k])*256 + d];
    }
}

// ---------------------------------------------------------------------------
extern "C" void kernel_launch(void* const* d_in, const int* in_sizes, int n_in,
                              void* d_out, int out_size)
{
    const float* vf    = (const float*)d_in[0];
    const float* qe    = (const float*)d_in[1];
    const float* pos   = (const float*)d_in[2];
    const float* mu_w1 = (const float*)d_in[3];
    const float* mu_b1 = (const float*)d_in[4];
    const float* mu_w2 = (const float*)d_in[5];
    const float* mu_b2 = (const float*)d_in[6];
    const float* ln_g  = (const float*)d_in[7];
    const float* ln_b  = (const float*)d_in[8];
    const float* sg_w1 = (const float*)d_in[9];
    const float* sg_b1 = (const float*)d_in[10];
    const float* sg_w2 = (const float*)d_in[11];
    const float* sg_b2 = (const float*)d_in[12];
    const float* sel_w1= (const float*)d_in[13];
    const float* sel_b1= (const float*)d_in[14];
    const float* sel_w2= (const float*)d_in[15];
    const float* sel_b2= (const float*)d_in[16];

    float* out      = (float*)d_out;
    float* out_rep  = out;               // [128,6,256]
    float* out_idx  = out + 196608;      // [128,6]
    float* out_dist = out + 197376;      // [128,1000]
    float* out_mu   = out + 325376;      // [128,256]
    float* out_sig  = out + 358144;      // [128,256]
    float* out_x    = out + 390912;      // [128,1000,256]

    static int s_attr_done = 0;
    if (!s_attr_done) {
        cudaFuncSetAttribute(k_rel, cudaFuncAttributeMaxDynamicSharedMemorySize, 180224);
        s_attr_done = 1;
    }

    k_wsplit<<<64, 256>>>(sel_w1);
    k_params<<<dim3(B_, 2), 256>>>(qe, mu_w1, mu_b1, mu_w2, mu_b2, ln_g, ln_b,
                                   sg_w1, sg_b1, sg_w2, sg_b2, sel_w1, sel_b1,
                                   out_mu, out_sig);
    k_rel<<<1000, 256, 180224>>>(vf, pos, out_mu, sel_w2, sel_b2,
                                 out_x, out_dist);
    k_select<<<B_, 256>>>(out_dist, out_x, out_rep, out_idx);
}